// round 17
// baseline (speedup 1.0000x reference)
#include <cuda_runtime.h>
#include <cuda_fp16.h>
#include <cstdint>

#define B_SZ   8
#define L_SEQ  4096
#define NDIM   256
#define HDIM   256
#define BL     (B_SZ * L_SEQ)        // 32768
#define CHUNK  128
#define NCHUNK (L_SEQ / CHUNK)       // 32
#define SEGS   4
#define SEGLEN (CHUNK / SEGS)        // 32
#define PX_BLOCKS ((BL * HDIM) / 2048)   // 4096 blocks, 8 floats/thread

// ---------------- scratch (device globals; no cudaMalloc allowed) ----------
__device__ __align__(256) __half2 g_Buh[(size_t)BL * NDIM];      // 33.5 MB (fp16 complex)
__device__ __align__(256) __half  g_xh[(size_t)BL * HDIM];       // 16 MB
__device__ __align__(256) __half  g_Sh[(size_t)BL * 2 * NDIM];   // 32 MB
__device__ __align__(256) __half  g_W2[2 * NDIM * HDIM];         // [512][256] fp16
__device__ __align__(256) __half  g_C2[HDIM * 2 * NDIM];         // [256][512] fp16
__device__ float2 g_Lam[NDIM];
__device__ float2 g_Lam32[NDIM];                    // Lambda^SEGLEN
__device__ float2 g_LamPowC[NCHUNK * NDIM];         // (Lambda^CHUNK)^k
__device__ float2 g_segE[(size_t)B_SZ * NCHUNK * SEGS * NDIM];  // 2 MB segment ends
__device__ float2 g_carryE[B_SZ * NCHUNK * NDIM];   // chunk-local end states

// ---------------- helpers ----------------------------------------------------
__device__ __forceinline__ void cp16(unsigned dst, const void* src) {
    asm volatile("cp.async.cg.shared.global [%0], [%1], 16;" :: "r"(dst), "l"(src));
}

__device__ __forceinline__ void ldm_x4(unsigned* r, unsigned addr) {
    asm volatile("ldmatrix.sync.aligned.m8n8.x4.shared.b16 {%0,%1,%2,%3}, [%4];"
                 : "=r"(r[0]), "=r"(r[1]), "=r"(r[2]), "=r"(r[3]) : "r"(addr));
}

__device__ __forceinline__ void mma_f16(float* c, const unsigned* a, const unsigned* b) {
    asm volatile("mma.sync.aligned.m16n8k16.row.col.f32.f16.f16.f32 "
                 "{%0,%1,%2,%3}, {%4,%5,%6,%7}, {%8,%9}, {%0,%1,%2,%3};"
                 : "+f"(c[0]), "+f"(c[1]), "+f"(c[2]), "+f"(c[3])
                 : "r"(a[0]), "r"(a[1]), "r"(a[2]), "r"(a[3]), "r"(b[0]), "r"(b[1]));
}

#define CP_COMMIT() asm volatile("cp.async.commit_group;" ::: "memory")
#define CP_WAIT1()  asm volatile("cp.async.wait_group 1;" ::: "memory")

// ---------------- single fused prep: x split + W/C rows + Lambda tables -----
__global__ __launch_bounds__(256) void prep_kernel(
    const float* __restrict__ x,
    const float* __restrict__ nu_log,
    const float* __restrict__ theta_log,
    const float* __restrict__ B_re,
    const float* __restrict__ B_im,
    const float* __restrict__ C_re,
    const float* __restrict__ C_im) {
    const int bid = blockIdx.x;
    if (bid < PX_BLOCKS) {
        size_t i = ((size_t)bid * 256 + threadIdx.x) * 8;
        float4 v0 = *(const float4*)(x + i);
        float4 v1 = *(const float4*)(x + i + 4);
        *(__half2*)(g_xh + i)     = __halves2half2(__float2half_rn(v0.x), __float2half_rn(v0.y));
        *(__half2*)(g_xh + i + 2) = __halves2half2(__float2half_rn(v0.z), __float2half_rn(v0.w));
        *(__half2*)(g_xh + i + 4) = __halves2half2(__float2half_rn(v1.x), __float2half_rn(v1.y));
        *(__half2*)(g_xh + i + 6) = __halves2half2(__float2half_rn(v1.z), __float2half_rn(v1.w));
    } else if (bid < PX_BLOCKS + NDIM) {
        int n = bid - PX_BLOCKS, h = threadIdx.x;
        float r = expf(-expf(nu_log[n]));
        float gamma = sqrtf(fmaxf(1.0f - r * r, 0.0f));
        g_W2[(2 * n) * HDIM + h]     = __float2half_rn(B_re[n * HDIM + h] * gamma);
        g_W2[(2 * n + 1) * HDIM + h] = __float2half_rn(B_im[n * HDIM + h] * gamma);
    } else if (bid < PX_BLOCKS + NDIM + HDIM) {
        int h = bid - PX_BLOCKS - NDIM, k = threadIdx.x;
        *(__half2*)(g_C2 + h * 512 + 2 * k) =
            __halves2half2(__float2half_rn(C_re[h * NDIM + k]),
                           __float2half_rn(-C_im[h * NDIM + k]));
    } else {
        int n = threadIdx.x;
        float nu  = expf(nu_log[n]);
        float th  = expf(theta_log[n]);
        float r   = expf(-nu);
        float lre = r * cosf(th);
        float lim = r * sinf(th);
        g_Lam[n] = make_float2(lre, lim);
        double pr = lre, pi = lim;
        #pragma unroll
        for (int s = 0; s < 5; ++s) {
            double nr = pr * pr - pi * pi;
            double ni = 2.0 * pr * pi;
            pr = nr; pi = ni;
        }
        g_Lam32[n] = make_float2((float)pr, (float)pi);
        #pragma unroll
        for (int s = 0; s < 2; ++s) {
            double nr = pr * pr - pi * pi;
            double ni = 2.0 * pr * pi;
            pr = nr; pi = ni;
        }
        double qr = 1.0, qi = 0.0;
        #pragma unroll 1
        for (int k = 0; k < NCHUNK; ++k) {
            g_LamPowC[k * NDIM + n] = make_float2((float)qr, (float)qi);
            double nr = qr * pr - qi * pi;
            double ni = qr * pi + qi * pr;
            qr = nr; qi = ni;
        }
    }
}

// ---------------- fp16 mma.sync GEMM -----------------------------------------
#define GSTAGES 3
#define GBK     64
#define A_STG_BYTES (128 * 128)
#define B_STG_BYTES (128 * 128)
#define SLOT_BYTES  (A_STG_BYTES + B_STG_BYTES)   // 32768
#define G_SMEM_BYTES (GSTAGES * SLOT_BYTES)       // 98304

template<int K, int NOUT, bool EPI, bool OUTH>
__device__ __forceinline__ void tc_gemm(
    const __half* __restrict__ A, const __half* __restrict__ B,
    void* __restrict__ outp,
    const __half* __restrict__ xres, const float* __restrict__ Dres)
{
    extern __shared__ __align__(1024) char smem[];
    const unsigned sbase = (unsigned)__cvta_generic_to_shared(smem);

    const int t = threadIdx.x, lane = t & 31, warp = t >> 5;
    const int wm = warp >> 1, wn = warp & 1;
    const int bm = blockIdx.y * 128, bn = blockIdx.x * 128;

    constexpr int NCH = K / GBK;

    float acc[2][8][4];
    #pragma unroll
    for (int i = 0; i < 2; ++i)
        #pragma unroll
        for (int j = 0; j < 8; ++j)
            #pragma unroll
            for (int q = 0; q < 4; ++q) acc[i][j][q] = 0.f;

    auto load_chunk = [&](int c) {
        const int slot = c % GSTAGES;
        const int kk0  = c * GBK;
        const unsigned abase = sbase + slot * SLOT_BYTES;
        const unsigned bbase = abase + A_STG_BYTES;
        #pragma unroll
        for (int i = 0; i < 4; ++i) {
            int idx = t + i * 256;
            int r = idx >> 3, g = idx & 7;
            cp16(abase + (unsigned)(r * 128 + ((g ^ (r & 7)) << 4)),
                 A + (size_t)(bm + r) * K + kk0 + g * 8);
        }
        #pragma unroll
        for (int i = 0; i < 4; ++i) {
            int idx = t + i * 256;
            int r = idx >> 3, g = idx & 7;
            cp16(bbase + (unsigned)(r * 128 + ((g ^ (r & 7)) << 4)),
                 B + (size_t)(bn + r) * K + kk0 + g * 8);
        }
    };

    load_chunk(0); CP_COMMIT();
    load_chunk(1); CP_COMMIT();

    const int ar0 = wm * 32 + (lane & 15);
    const int ar1 = ar0 + 16;
    const int akc = lane >> 4;
    const int brb = wn * 64 + (lane & 7) + ((lane >> 4) << 3);
    const int bkc = (lane >> 3) & 1;

    #pragma unroll 1
    for (int c = 0; c < NCH; ++c) {
        CP_WAIT1();
        __syncthreads();

        if (c + 2 < NCH) load_chunk(c + 2);
        CP_COMMIT();

        const int slot = c % GSTAGES;
        const unsigned abase = sbase + slot * SLOT_BYTES;
        const unsigned bbase = abase + A_STG_BYTES;

        #pragma unroll
        for (int kk = 0; kk < GBK; kk += 16) {
            unsigned a[2][4], b[4][4];
            {
                int kc = (kk >> 3) + akc;
                ldm_x4(a[0], abase + (unsigned)(ar0 * 128 + ((kc ^ (ar0 & 7)) << 4)));
                ldm_x4(a[1], abase + (unsigned)(ar1 * 128 + ((kc ^ (ar1 & 7)) << 4)));
            }
            #pragma unroll
            for (int p = 0; p < 4; ++p) {
                int br = brb + p * 16;
                int kc = (kk >> 3) + bkc;
                ldm_x4(b[p], bbase + (unsigned)(br * 128 + ((kc ^ (br & 7)) << 4)));
            }
            #pragma unroll
            for (int mt = 0; mt < 2; ++mt)
                #pragma unroll
                for (int nt = 0; nt < 8; ++nt)
                    mma_f16(acc[mt][nt], a[mt], &b[nt >> 1][(nt & 1) * 2]);
        }
    }

    #pragma unroll
    for (int mt = 0; mt < 2; ++mt)
        #pragma unroll
        for (int nt = 0; nt < 8; ++nt) {
            const int row = bm + wm * 32 + mt * 16 + (lane >> 2);
            const int col = bn + wn * 64 + nt * 8 + (lane & 3) * 2;
            const float* c = acc[mt][nt];
            if (OUTH) {
                __half2* out = (__half2*)outp;
                out[(size_t)row * (NOUT / 2) + (col >> 1)] =
                    __halves2half2(__float2half_rn(c[0]), __float2half_rn(c[1]));
                out[(size_t)(row + 8) * (NOUT / 2) + (col >> 1)] =
                    __halves2half2(__float2half_rn(c[2]), __float2half_rn(c[3]));
            } else if (EPI) {
                float* out = (float*)outp;
                float2 d  = *(const float2*)(Dres + col);
                float2 x0 = __half22float2(*(const __half2*)(xres + (size_t)row * NOUT + col));
                float2 x1 = __half22float2(*(const __half2*)(xres + (size_t)(row + 8) * NOUT + col));
                *(float2*)(out + (size_t)row * NOUT + col) =
                    make_float2(c[0] + x0.x * d.x, c[1] + x0.y * d.y);
                *(float2*)(out + (size_t)(row + 8) * NOUT + col) =
                    make_float2(c[2] + x1.x * d.x, c[3] + x1.y * d.y);
            } else {
                float* out = (float*)outp;
                *(float2*)(out + (size_t)row * NOUT + col)       = make_float2(c[0], c[1]);
                *(float2*)(out + (size_t)(row + 8) * NOUT + col) = make_float2(c[2], c[3]);
            }
        }
}

__global__ __launch_bounds__(256, 2) void gemm1_kernel() {
    tc_gemm<HDIM, 2 * NDIM, false, true>(g_xh, g_W2, (void*)g_Buh, nullptr, nullptr);
}

__global__ __launch_bounds__(256, 2) void gemm2_kernel(const float* __restrict__ D,
                                                       float* __restrict__ y) {
    tc_gemm<2 * NDIM, HDIM, true, false>(g_Sh, g_C2, (void*)y, g_xh, D);
}

// ---------------- scanA: segment ends + chunk-end carries -------------------
__global__ __launch_bounds__(1024) void scanA_kernel() {
    __shared__ float2 e[SEGS * NDIM];
    const int tid = threadIdx.x;
    const int col = tid & 255, seg = tid >> 8;
    const int bc = blockIdx.x;
    const float2 lam = g_Lam[col];
    float2 s = make_float2(0.f, 0.f);
    const __half2* p = g_Buh + (size_t)bc * CHUNK * NDIM
                             + (size_t)seg * SEGLEN * NDIM + col;

    #pragma unroll 1
    for (int j0 = 0; j0 < SEGLEN; j0 += 8) {
        float2 b[8];
        #pragma unroll
        for (int u = 0; u < 8; ++u)
            b[u] = __half22float2(p[(size_t)(j0 + u) * NDIM]);
        #pragma unroll
        for (int u = 0; u < 8; ++u) {
            float sx = fmaf(lam.x, s.x, fmaf(-lam.y, s.y, b[u].x));
            float sy = fmaf(lam.x, s.y, fmaf( lam.y, s.x, b[u].y));
            s = make_float2(sx, sy);
        }
    }
    e[tid] = s;
    g_segE[(size_t)bc * SEGS * NDIM + tid] = s;
    __syncthreads();

    if (tid < NDIM) {
        const float2 l32 = g_Lam32[tid];
        float2 acc = e[tid];
        #pragma unroll
        for (int sg = 1; sg < SEGS; ++sg) {
            float2 es = e[sg * NDIM + tid];
            float ax = fmaf(l32.x, acc.x, fmaf(-l32.y, acc.y, es.x));
            float ay = fmaf(l32.x, acc.y, fmaf( l32.y, acc.x, es.y));
            acc = make_float2(ax, ay);
        }
        g_carryE[(size_t)bc * NDIM + tid] = acc;
    }
}

// ---------------- scanC: parallel-prologue rescan, emit fp16 states ---------
__global__ __launch_bounds__(1024) void scanC_kernel() {
    __shared__ float2 part[SEGS * NDIM];     // partial carry sums
    __shared__ float2 cs[SEGS * NDIM];       // per-segment carry-in
    const int tid = threadIdx.x;
    const int col = tid & 255, seg = tid >> 8;
    const int bc = blockIdx.x;
    const int b = bc >> 5, c = bc & 31;      // NCHUNK = 32
    const float2 lam = g_Lam[col];
    const __half2* p = g_Buh + (size_t)bc * CHUNK * NDIM
                             + (size_t)seg * SEGLEN * NDIM + col;

    // hoisted first Buh batch (carry-independent; hides DRAM latency)
    float2 pre[8];
    #pragma unroll
    for (int u = 0; u < 8; ++u)
        pre[u] = __half22float2(p[(size_t)u * NDIM]);

    // prologue: ALL 1024 threads compute strided partials of the carry sum
    {
        float2 cin = make_float2(0.f, 0.f);
        #pragma unroll 2
        for (int cp = seg; cp < c; cp += SEGS) {
            float2 P = g_LamPowC[(c - 1 - cp) * NDIM + col];
            float2 E = g_carryE[((size_t)b * NCHUNK + cp) * NDIM + col];
            cin.x = fmaf(P.x, E.x, fmaf(-P.y, E.y, cin.x));
            cin.y = fmaf(P.x, E.y, fmaf( P.y, E.x, cin.y));
        }
        part[tid] = cin;
    }
    __syncthreads();

    // reduce partials + per-segment carry chain (threads < 256)
    if (tid < NDIM) {
        float2 cc = part[tid];
        #pragma unroll
        for (int sg = 1; sg < SEGS; ++sg) {
            float2 pv = part[sg * NDIM + tid];
            cc.x += pv.x; cc.y += pv.y;
        }
        const float2 l32 = g_Lam32[tid];
        cs[tid] = cc;
        #pragma unroll
        for (int sg = 0; sg < SEGS - 1; ++sg) {
            float2 es = g_segE[(size_t)bc * SEGS * NDIM + sg * NDIM + tid];
            float cx = fmaf(l32.x, cc.x, fmaf(-l32.y, cc.y, es.x));
            float cy = fmaf(l32.x, cc.y, fmaf( l32.y, cc.x, es.y));
            cc = make_float2(cx, cy);
            cs[(sg + 1) * NDIM + tid] = cc;
        }
    }
    __syncthreads();

    // rescan from carry-in, write fp16 states (first batch from registers)
    {
        float2 s = cs[seg * NDIM + col];
        __half2* o = (__half2*)g_Sh + (size_t)bc * CHUNK * NDIM
                                    + (size_t)seg * SEGLEN * NDIM + col;
        #pragma unroll
        for (int u = 0; u < 8; ++u) {
            float sx = fmaf(lam.x, s.x, fmaf(-lam.y, s.y, pre[u].x));
            float sy = fmaf(lam.x, s.y, fmaf( lam.y, s.x, pre[u].y));
            s = make_float2(sx, sy);
            o[(size_t)u * NDIM] =
                __halves2half2(__float2half_rn(sx), __float2half_rn(sy));
        }
        #pragma unroll 1
        for (int j0 = 8; j0 < SEGLEN; j0 += 8) {
            float2 b8[8];
            #pragma unroll
            for (int u = 0; u < 8; ++u)
                b8[u] = __half22float2(p[(size_t)(j0 + u) * NDIM]);
            #pragma unroll
            for (int u = 0; u < 8; ++u) {
                float sx = fmaf(lam.x, s.x, fmaf(-lam.y, s.y, b8[u].x));
                float sy = fmaf(lam.x, s.y, fmaf( lam.y, s.x, b8[u].y));
                s = make_float2(sx, sy);
                o[(size_t)(j0 + u) * NDIM] =
                    __halves2half2(__float2half_rn(sx), __float2half_rn(sy));
            }
        }
    }
}

// ---------------- launch -----------------------------------------------------
extern "C" void kernel_launch(void* const* d_in, const int* in_sizes, int n_in,
                              void* d_out, int out_size) {
    const float* x         = (const float*)d_in[0];
    const float* B_re      = (const float*)d_in[1];
    const float* B_im      = (const float*)d_in[2];
    const float* C_re      = (const float*)d_in[3];
    const float* C_im      = (const float*)d_in[4];
    const float* nu_log    = (const float*)d_in[5];
    const float* theta_log = (const float*)d_in[6];
    const float* D         = (const float*)d_in[7];
    float* y = (float*)d_out;

    cudaFuncSetAttribute(gemm1_kernel,
                         cudaFuncAttributeMaxDynamicSharedMemorySize, G_SMEM_BYTES);
    cudaFuncSetAttribute(gemm2_kernel,
                         cudaFuncAttributeMaxDynamicSharedMemorySize, G_SMEM_BYTES);

    prep_kernel<<<PX_BLOCKS + NDIM + HDIM + 1, 256>>>(x, nu_log, theta_log,
                                                      B_re, B_im, C_re, C_im);
    gemm1_kernel<<<dim3((2 * NDIM) / 128, BL / 128), 256, G_SMEM_BYTES>>>();
    scanA_kernel<<<B_SZ * NCHUNK, 1024>>>();
    scanC_kernel<<<B_SZ * NCHUNK, 1024>>>();
    gemm2_kernel<<<dim3(HDIM / 128, BL / 128), 256, G_SMEM_BYTES>>>(D, y);
}